// round 10
// baseline (speedup 1.0000x reference)
#include <cuda_runtime.h>
#include <math.h>

#define TT  64
#define BB  16
#define II  512
#define HH  512
#define OO  512
#define NN  256
#define WD  64
#define RR  4
#define NIN 768
#define IFW 471
#define FEPS 1e-6f

// ---------------- persistent state -------------
__device__ float g_M [BB*NN*WD];
__device__ float g_u [BB*NN];
__device__ float g_p [2][BB*NN];
__device__ float g_ww[BB*NN];
__device__ float g_L [2][BB*NN*NN];    // double-buffered (8MB)
__device__ float g_rw[BB*RR*NN];
__device__ float g_rv[BB*RR*WD];
__device__ float g_h  [BB*HH];
__device__ float g_po [BB*OO];
__device__ float g_if [BB*IFW];
__device__ float g_fwd[BB*RR*NN];
__device__ float g_bwd[BB*RR*NN];
__device__ float g_simw [BB*NN];
__device__ float g_alloc[BB*NN];
__device__ float g_rsim[BB*RR*NN];

__device__ __forceinline__ float sigm(float x){ return 1.f/(1.f+expf(-x)); }
__device__ __forceinline__ float oneplus(float x){ return 1.f + (x > 20.f ? x : log1pf(expf(x))); }

// ---------------- init ------------------
__global__ void k_init(){
    int i0 = blockIdx.x*blockDim.x + threadIdx.x;
    int st = gridDim.x*blockDim.x;
    for (int i=i0;i<BB*NN*NN;i+=st){ g_L[0][i]=0.f; g_L[1][i]=0.f; }
    for (int i=i0;i<BB*NN*WD;i+=st) g_M[i]=1e-6f;
    for (int i=i0;i<BB*NN;i+=st){ g_u[i]=0.f; g_p[0][i]=0.f; g_p[1][i]=0.f; g_ww[i]=0.f; }
    for (int i=i0;i<BB*RR*NN;i+=st) g_rw[i]=0.f;
    for (int i=i0;i<BB*RR*WD;i+=st) g_rv[i]=0.f;
}

// ---------------- K1: out(t-1) = po + rv@Wm  AND  h = relu([x,rv]@W_hid + b) ----
__global__ __launch_bounds__(256) void k_hidout(const float* __restrict__ x,
        const float* __restrict__ Wh, const float* __restrict__ bh,
        const float* __restrict__ Wm, float* __restrict__ out, int t){
    extern __shared__ __align__(16) float s[];
    float* sp = s + BB*NIN;
    int tid = threadIdx.x;
    #pragma unroll
    for (int b=0;b<BB;b++)
        for (int k=tid;k<NIN;k+=256)
            s[b*NIN+k] = (k<II) ? x[(t*BB+b)*II + k] : g_rv[b*(RR*WD) + (k-II)];
    __syncthreads();

    int kg = tid>>4, jl = tid&15;
    int j = blockIdx.x*16 + jl;

    if (t > 0){
        const float* Wc = Wm + j;
        float acc[BB];
        #pragma unroll
        for (int b=0;b<BB;b++) acc[b]=0.f;
        int k0 = kg*16;
        #pragma unroll
        for (int kk=0; kk<16; kk+=4){
            int k = k0+kk;
            float w0 = Wc[(k+0)*OO], w1 = Wc[(k+1)*OO], w2 = Wc[(k+2)*OO], w3 = Wc[(k+3)*OO];
            #pragma unroll
            for (int b=0;b<BB;b++){
                float4 v = *reinterpret_cast<const float4*>(&s[b*NIN + II + k]);
                acc[b] = fmaf(v.x,w0, fmaf(v.y,w1, fmaf(v.z,w2, fmaf(v.w,w3, acc[b]))));
            }
        }
        __syncthreads();
        #pragma unroll
        for (int b=0;b<BB;b++) sp[kg*256 + b*16 + jl] = acc[b];
        __syncthreads();
        {
            int p = tid;
            int b = p>>4, jj = p&15;
            int jo = blockIdx.x*16 + jj;
            float sum = g_po[b*OO + jo];
            #pragma unroll
            for (int g=0;g<16;g++) sum += sp[g*256 + p];
            out[((t-1)*BB + b)*OO + jo] = sum;
        }
        __syncthreads();
    }

    const float* Wc = Wh + j;
    float acc[BB];
    #pragma unroll
    for (int b=0;b<BB;b++) acc[b]=0.f;
    int k0 = kg*48;
    #pragma unroll 3
    for (int kk=0; kk<48; kk+=4){
        int k = k0+kk;
        float w0 = Wc[(k+0)*HH], w1 = Wc[(k+1)*HH], w2 = Wc[(k+2)*HH], w3 = Wc[(k+3)*HH];
        #pragma unroll
        for (int b=0;b<BB;b++){
            float4 v = *reinterpret_cast<const float4*>(&s[b*NIN+k]);
            acc[b] = fmaf(v.x,w0, fmaf(v.y,w1, fmaf(v.z,w2, fmaf(v.w,w3, acc[b]))));
        }
    }
    __syncthreads();
    #pragma unroll
    for (int b=0;b<BB;b++) sp[kg*256 + b*16 + jl] = acc[b];
    __syncthreads();
    {
        int p = tid;
        int b = p>>4, jj = p&15;
        int jo = blockIdx.x*16 + jj;
        float sum = bh[jo];
        #pragma unroll
        for (int g=0;g<16;g++) sum += sp[g*256 + p];
        g_h[b*HH + jo] = fmaxf(sum, 0.f);
    }
}

// ---------------- K2: pre_out = h@W_out ; iface = h@W_iface ---------------------
__global__ __launch_bounds__(256) void k_proj(const float* __restrict__ Wo,
                                              const float* __restrict__ Wi){
    extern __shared__ __align__(16) float s[];
    float* sp = s + BB*HH;
    int tid = threadIdx.x;
    for (int i=tid;i<BB*HH;i+=256) s[i] = g_h[i];
    __syncthreads();

    int kg = tid>>4, jl = tid&15;
    int j = blockIdx.x*16 + jl;
    const float* Wc; int stride;
    if (j < OO){ Wc = Wo + j; stride = OO; }
    else { int jj = j - OO; if (jj > IFW-1) jj = IFW-1; Wc = Wi + jj; stride = IFW; }
    float acc[BB];
    #pragma unroll
    for (int b=0;b<BB;b++) acc[b]=0.f;
    int k0 = kg*32;
    #pragma unroll 2
    for (int kk=0; kk<32; kk+=4){
        int k = k0+kk;
        float w0 = Wc[(k+0)*stride], w1 = Wc[(k+1)*stride];
        float w2 = Wc[(k+2)*stride], w3 = Wc[(k+3)*stride];
        #pragma unroll
        for (int b=0;b<BB;b++){
            float4 v = *reinterpret_cast<const float4*>(&s[b*HH+k]);
            acc[b] = fmaf(v.x,w0, fmaf(v.y,w1, fmaf(v.z,w2, fmaf(v.w,w3, acc[b]))));
        }
    }
    __syncthreads();
    #pragma unroll
    for (int b=0;b<BB;b++) sp[kg*256 + b*16 + jl] = acc[b];
    __syncthreads();
    {
        int p = tid;
        int b = p>>4, jj = p&15;
        int jo = blockIdx.x*16 + jj;
        float sum = 0.f;
        #pragma unroll
        for (int g=0;g<16;g++) sum += sp[g*256 + p];
        if (jo < OO) g_po[b*OO + jo] = sum;
        else if (jo - OO < IFW) g_if[b*IFW + (jo-OO)] = sum;
    }
}

// ---------------- K2b: write-content cosine + (parallel) usage/rank/alloc -------
// grid (9,16) x 256. x<8: sim for 32 slots; x==8: usage update + rank sort + alloc.
__global__ __launch_bounds__(256) void k_wsim(){
    __shared__ float shA[256];   // wk_s (sim) / sk (alloc)
    __shared__ float shB[256];   // ss
    __shared__ float shC[256];   // sc
    __shared__ float red8[8];
    int b = blockIdx.y, tid = threadIdx.x;
    int wi = tid>>5, l = tid&31;
    const float* ifc = g_if + b*IFW;

    if (blockIdx.x < 8){
        if (tid < 64) shA[tid] = ifc[260+tid];
        __syncthreads();
        float k0 = shA[l], k1 = shA[l+32];
        float kk = k0*k0 + k1*k1;
        int nb = blockIdx.x*32 + wi*4;
        float ns[4], dt[4];
        #pragma unroll
        for (int i=0;i<4;i++){
            const float* Mr = g_M + (b*NN + nb + i)*WD;
            float m0 = Mr[l], m1 = Mr[l+32];
            ns[i] = m0*m0 + m1*m1;
            dt[i] = m0*k0 + m1*k1;
        }
        #pragma unroll
        for (int o=16;o;o>>=1){
            kk += __shfl_xor_sync(0xffffffffu, kk, o);
            #pragma unroll
            for (int i=0;i<4;i++){
                ns[i] += __shfl_xor_sync(0xffffffffu, ns[i], o);
                dt[i] += __shfl_xor_sync(0xffffffffu, dt[i], o);
            }
        }
        if (l==0){
            float dk = sqrtf(kk) + FEPS;
            #pragma unroll
            for (int i=0;i<4;i++)
                g_simw[b*NN + nb + i] = dt[i] / ((sqrtf(ns[i])+FEPS) * dk);
        }
    } else {
        // usage update + stable rank + exclusive cumprod -> allocation weights
        float fg0 = sigm(ifc[453]), fg1 = sigm(ifc[454]);
        float fg2 = sigm(ifc[455]), fg3 = sigm(ifc[456]);
        float u   = g_u [b*NN + tid];
        float wwo = g_ww[b*NN + tid];
        float ret = (1.f - fg0*g_rw[(b*RR+0)*NN+tid])
                  * (1.f - fg1*g_rw[(b*RR+1)*NN+tid])
                  * (1.f - fg2*g_rw[(b*RR+2)*NN+tid])
                  * (1.f - fg3*g_rw[(b*RR+3)*NN+tid]);
        float un = (u + wwo - u*wwo) * ret;
        g_u[b*NN + tid] = un;
        shA[tid] = un;
        __syncthreads();
        int rank = 0;
        #pragma unroll 4
        for (int jx=0;jx<256;jx++){
            float kj = shA[jx];
            rank += (int)((kj < un) || (kj == un && jx < tid));
        }
        shB[rank] = un;
        __syncthreads();
        float pscan = shB[tid];
        #pragma unroll
        for (int o=1;o<32;o<<=1){
            float t2 = __shfl_up_sync(0xffffffffu, pscan, o);
            if (l >= o) pscan *= t2;
        }
        if (l==31) red8[wi] = pscan;
        __syncthreads();
        float wpre = 1.f;
        for (int g=0; g<wi; g++) wpre *= red8[g];
        float incl = pscan * wpre;
        float prev = __shfl_up_sync(0xffffffffu, incl, 1);
        float excl = (l==0) ? wpre : prev;
        shC[tid] = excl;
        __syncthreads();
        g_alloc[b*NN + tid] = (1.f - un) * shC[rank];
    }
}

// ---------------- K3: write-content softmax, ww, precedence ---------------------
__global__ __launch_bounds__(256) void k_control(int par){
    __shared__ float red8[8];
    int b = blockIdx.x, tid = threadIdx.x;
    int wi = tid>>5, l = tid&31;
    const float* ifc = g_if + b*IFW;

    float wb = oneplus(ifc[324]);
    float logit = wb * g_simw[b*NN + tid];
    float mx = logit;
    #pragma unroll
    for (int o=16;o;o>>=1) mx = fmaxf(mx, __shfl_xor_sync(0xffffffffu, mx, o));
    if (l==0) red8[wi] = mx;
    __syncthreads();
    float gmx = red8[0];
    #pragma unroll
    for (int g=1;g<8;g++) gmx = fmaxf(gmx, red8[g]);
    __syncthreads();
    float e = expf(logit - gmx);
    float sm = e;
    #pragma unroll
    for (int o=16;o;o>>=1) sm += __shfl_xor_sync(0xffffffffu, sm, o);
    if (l==0) red8[wi] = sm;
    __syncthreads();
    float tot = 0.f;
    #pragma unroll
    for (int g=0;g<8;g++) tot += red8[g];
    float cw = e / tot;

    float ag = sigm(ifc[457]), wg = sigm(ifc[458]);
    float wwn = wg * (ag*g_alloc[b*NN + tid] + (1.f-ag)*cw);
    g_ww[b*NN + tid] = wwn;

    __syncthreads();
    float sw = wwn;
    #pragma unroll
    for (int o=16;o;o>>=1) sw += __shfl_xor_sync(0xffffffffu, sw, o);
    if (l==0) red8[wi] = sw;
    __syncthreads();
    float S = 0.f;
    #pragma unroll
    for (int g=0;g<8;g++) S += red8[g];
    float po = g_p[par][b*NN + tid];
    g_p[par^1][b*NN + tid] = (1.f - S)*po + wwn;
}

// ---------------- K4: M update + read sims + L row update + fwd + bwd -----------
// grid (33,16) x 256. x<32: warp-per-L-row; x==32: bwd column scan on L_old.
__global__ __launch_bounds__(256) void k_meml(int par){
    int b = blockIdx.y;
    int tid = threadIdx.x, wi = tid>>5, l = tid&31;
    const float* ifc = g_if + b*IFW;

    if (blockIdx.x < 32){
        int n0 = blockIdx.x*8;
        __shared__ float4 rk4[64];
        __shared__ float ev_s[64], wv_s[64];
        if (tid < 64){
            rk4[tid] = make_float4(ifc[tid], ifc[64+tid], ifc[128+tid], ifc[192+tid]);
            ev_s[tid] = sigm(ifc[325 + tid]);
            wv_s[tid] = ifc[389 + tid];
        }
        __syncthreads();

        int n = n0 + wi;
        float wwn = g_ww[b*NN + n];
        float* Mr = g_M + (b*NN + n)*WD;
        float m0 = Mr[l], m1 = Mr[l+32];
        m0 = m0*(1.f - wwn*ev_s[l   ]) + wwn*wv_s[l   ];
        m1 = m1*(1.f - wwn*ev_s[l+32]) + wwn*wv_s[l+32];
        Mr[l] = m0; Mr[l+32] = m1;

        float4 a = rk4[l], c = rk4[l+32];
        float ns = m0*m0 + m1*m1;
        float d0 = m0*a.x + m1*c.x;
        float d1 = m0*a.y + m1*c.y;
        float d2 = m0*a.z + m1*c.z;
        float d3 = m0*a.w + m1*c.w;
        #pragma unroll
        for (int o=16;o;o>>=1){
            ns += __shfl_xor_sync(0xffffffffu, ns, o);
            d0 += __shfl_xor_sync(0xffffffffu, d0, o);
            d1 += __shfl_xor_sync(0xffffffffu, d1, o);
            d2 += __shfl_xor_sync(0xffffffffu, d2, o);
            d3 += __shfl_xor_sync(0xffffffffu, d3, o);
        }
        if (l==0){
            float inv = 1.f/(sqrtf(ns)+FEPS);
            g_rsim[(b*RR+0)*NN+n] = d0*inv;
            g_rsim[(b*RR+1)*NN+n] = d1*inv;
            g_rsim[(b*RR+2)*NN+n] = d2*inv;
            g_rsim[(b*RR+3)*NN+n] = d3*inv;
        }

        const float* Lo = g_L[par]   + (b*NN + n)*NN;
        float*       Ln = g_L[par^1] + (b*NN + n)*NN;
        const float* pw  = g_p[par] + b*NN;
        const float* wwp = g_ww + b*NN;
        const float* rwp = g_rw + b*RR*NN;
        float f0=0.f,f1=0.f,f2=0.f,f3=0.f;
        #pragma unroll
        for (int k=0;k<8;k++){
            int m = l + k*32;
            float lo = Lo[m];
            float ln = (1.f - wwn - wwp[m])*lo + wwn*pw[m];
            if (m == n) ln = 0.f;
            Ln[m] = ln;
            f0 = fmaf(ln, rwp[0*NN+m], f0);
            f1 = fmaf(ln, rwp[1*NN+m], f1);
            f2 = fmaf(ln, rwp[2*NN+m], f2);
            f3 = fmaf(ln, rwp[3*NN+m], f3);
        }
        #pragma unroll
        for (int o=16;o;o>>=1){
            f0 += __shfl_xor_sync(0xffffffffu, f0, o);
            f1 += __shfl_xor_sync(0xffffffffu, f1, o);
            f2 += __shfl_xor_sync(0xffffffffu, f2, o);
            f3 += __shfl_xor_sync(0xffffffffu, f3, o);
        }
        if (l==0){
            g_fwd[(b*RR+0)*NN+n]=f0; g_fwd[(b*RR+1)*NN+n]=f1;
            g_fwd[(b*RR+2)*NN+n]=f2; g_fwd[(b*RR+3)*NN+n]=f3;
        }
    } else {
        // bwd[r][n] = (1-ww[n])*A - B + p[n]*(C - ww[n]*rw[r][n])
        // A = sum_m Lold[m][n] rw[r][m]; B = sum_m Lold[m][n] (ww*rw)[r][m]; C = sum_m ww[m] rw[r][m]
        __shared__ float4 rw4[256], wr4[256];
        __shared__ float sww[256], sp_[256];
        __shared__ float4 redC[8];
        const float* rwp = g_rw + b*RR*NN;
        float wwm = g_ww[b*NN + tid];
        float4 r4 = make_float4(rwp[tid], rwp[NN+tid], rwp[2*NN+tid], rwp[3*NN+tid]);
        float4 w4 = make_float4(wwm*r4.x, wwm*r4.y, wwm*r4.z, wwm*r4.w);
        rw4[tid] = r4; wr4[tid] = w4;
        sww[tid] = wwm; sp_[tid] = g_p[par][b*NN + tid];
        // C reduction
        float cx=w4.x, cy=w4.y, cz=w4.z, cw=w4.w;
        #pragma unroll
        for (int o=16;o;o>>=1){
            cx += __shfl_xor_sync(0xffffffffu, cx, o);
            cy += __shfl_xor_sync(0xffffffffu, cy, o);
            cz += __shfl_xor_sync(0xffffffffu, cz, o);
            cw += __shfl_xor_sync(0xffffffffu, cw, o);
        }
        if (l==0) redC[wi] = make_float4(cx,cy,cz,cw);
        __syncthreads();
        float4 C = make_float4(0,0,0,0);
        #pragma unroll
        for (int g=0;g<8;g++){
            float4 r = redC[g];
            C.x+=r.x; C.y+=r.y; C.z+=r.z; C.w+=r.w;
        }
        float4 A = make_float4(0,0,0,0), Bv = make_float4(0,0,0,0);
        const float* Lo = g_L[par] + b*NN*NN;
        #pragma unroll 8
        for (int m=0;m<NN;m++){
            float lv = Lo[m*NN + tid];
            float4 rr = rw4[m]; float4 ww2 = wr4[m];
            A.x = fmaf(lv, rr.x, A.x);  A.y = fmaf(lv, rr.y, A.y);
            A.z = fmaf(lv, rr.z, A.z);  A.w = fmaf(lv, rr.w, A.w);
            Bv.x = fmaf(lv, ww2.x, Bv.x); Bv.y = fmaf(lv, ww2.y, Bv.y);
            Bv.z = fmaf(lv, ww2.z, Bv.z); Bv.w = fmaf(lv, ww2.w, Bv.w);
        }
        float wwn = sww[tid], pn = sp_[tid];
        float4 rn = rw4[tid];
        float om = 1.f - wwn;
        g_bwd[(b*RR+0)*NN+tid] = om*A.x - Bv.x + pn*(C.x - wwn*rn.x);
        g_bwd[(b*RR+1)*NN+tid] = om*A.y - Bv.y + pn*(C.y - wwn*rn.y);
        g_bwd[(b*RR+2)*NN+tid] = om*A.z - Bv.z + pn*(C.z - wwn*rn.z);
        g_bwd[(b*RR+3)*NN+tid] = om*A.w - Bv.w + pn*(C.w - wwn*rn.w);
    }
}

// ---------------- K5: read softmax, rw_new, rv_new ------------------------------
__global__ __launch_bounds__(256) void k_read(){
    __shared__ float4 rwn4[256];
    __shared__ float4 red4[8];
    __shared__ float s_knd[4];
    __shared__ float partial[8*256];
    int b = blockIdx.x, tid = threadIdx.x, wi = tid>>5, l = tid&31;
    const float* ifc = g_if + b*IFW;

    if (wi < 4){
        float k0 = ifc[wi*64 + l], k1 = ifc[wi*64 + l + 32];
        float ss = k0*k0 + k1*k1;
        #pragma unroll
        for (int o=16;o;o>>=1) ss += __shfl_xor_sync(0xffffffffu, ss, o);
        if (l==0) s_knd[wi] = sqrtf(ss) + FEPS;
    }
    __syncthreads();

    float lg0 = oneplus(ifc[256]) * g_rsim[(b*RR+0)*NN+tid] / s_knd[0];
    float lg1 = oneplus(ifc[257]) * g_rsim[(b*RR+1)*NN+tid] / s_knd[1];
    float lg2 = oneplus(ifc[258]) * g_rsim[(b*RR+2)*NN+tid] / s_knd[2];
    float lg3 = oneplus(ifc[259]) * g_rsim[(b*RR+3)*NN+tid] / s_knd[3];

    float m0=lg0,m1=lg1,m2=lg2,m3=lg3;
    #pragma unroll
    for (int o=16;o;o>>=1){
        m0=fmaxf(m0,__shfl_xor_sync(0xffffffffu,m0,o));
        m1=fmaxf(m1,__shfl_xor_sync(0xffffffffu,m1,o));
        m2=fmaxf(m2,__shfl_xor_sync(0xffffffffu,m2,o));
        m3=fmaxf(m3,__shfl_xor_sync(0xffffffffu,m3,o));
    }
    if (l==0) red4[wi] = make_float4(m0,m1,m2,m3);
    __syncthreads();
    float4 mxv = red4[0];
    #pragma unroll
    for (int g=1;g<8;g++){
        float4 r = red4[g];
        mxv.x=fmaxf(mxv.x,r.x); mxv.y=fmaxf(mxv.y,r.y);
        mxv.z=fmaxf(mxv.z,r.z); mxv.w=fmaxf(mxv.w,r.w);
    }
    __syncthreads();
    float e0=expf(lg0-mxv.x), e1=expf(lg1-mxv.y), e2=expf(lg2-mxv.z), e3=expf(lg3-mxv.w);
    float s0=e0,s1=e1,s2=e2,s3=e3;
    #pragma unroll
    for (int o=16;o;o>>=1){
        s0+=__shfl_xor_sync(0xffffffffu,s0,o);
        s1+=__shfl_xor_sync(0xffffffffu,s1,o);
        s2+=__shfl_xor_sync(0xffffffffu,s2,o);
        s3+=__shfl_xor_sync(0xffffffffu,s3,o);
    }
    if (l==0) red4[wi] = make_float4(s0,s1,s2,s3);
    __syncthreads();
    float4 tv = make_float4(0,0,0,0);
    #pragma unroll
    for (int g=0;g<8;g++){
        float4 r = red4[g];
        tv.x+=r.x; tv.y+=r.y; tv.z+=r.z; tv.w+=r.w;
    }
    float rc0=e0/tv.x, rc1=e1/tv.y, rc2=e2/tv.z, rc3=e3/tv.w;

    float rm[4][3];
    #pragma unroll
    for (int r=0;r<4;r++){
        float v0=ifc[459+3*r], v1=ifc[460+3*r], v2=ifc[461+3*r];
        float mxg = fmaxf(v0, fmaxf(v1, v2));
        float a0=expf(v0-mxg), a1=expf(v1-mxg), a2=expf(v2-mxg);
        float inv = 1.f/(a0+a1+a2);
        rm[r][0]=a0*inv; rm[r][1]=a1*inv; rm[r][2]=a2*inv;
    }
    float bw0 = g_bwd[(b*RR+0)*NN+tid], bw1 = g_bwd[(b*RR+1)*NN+tid];
    float bw2 = g_bwd[(b*RR+2)*NN+tid], bw3 = g_bwd[(b*RR+3)*NN+tid];
    float fw0 = g_fwd[(b*RR+0)*NN+tid], fw1 = g_fwd[(b*RR+1)*NN+tid];
    float fw2 = g_fwd[(b*RR+2)*NN+tid], fw3 = g_fwd[(b*RR+3)*NN+tid];

    float w0 = rm[0][0]*bw0 + rm[0][1]*rc0 + rm[0][2]*fw0;
    float w1 = rm[1][0]*bw1 + rm[1][1]*rc1 + rm[1][2]*fw1;
    float w2 = rm[2][0]*bw2 + rm[2][1]*rc2 + rm[2][2]*fw2;
    float w3 = rm[3][0]*bw3 + rm[3][1]*rc3 + rm[3][2]*fw3;
    g_rw[(b*RR+0)*NN+tid]=w0; g_rw[(b*RR+1)*NN+tid]=w1;
    g_rw[(b*RR+2)*NN+tid]=w2; g_rw[(b*RR+3)*NN+tid]=w3;
    rwn4[tid] = make_float4(w0,w1,w2,w3);
    __syncthreads();

    float a0x=0.f,a0y=0.f,a0z=0.f,a0w=0.f;
    float a1x=0.f,a1y=0.f,a1z=0.f,a1w=0.f;
    const float* Mb = g_M + b*NN*WD;
    #pragma unroll 4
    for (int q=0;q<32;q++){
        int n = wi*32 + q;
        float lv0 = Mb[n*WD + l];
        float lv1 = Mb[n*WD + l + 32];
        float4 rn = rwn4[n];
        a0x=fmaf(lv0,rn.x,a0x); a0y=fmaf(lv0,rn.y,a0y);
        a0z=fmaf(lv0,rn.z,a0z); a0w=fmaf(lv0,rn.w,a0w);
        a1x=fmaf(lv1,rn.x,a1x); a1y=fmaf(lv1,rn.y,a1y);
        a1z=fmaf(lv1,rn.z,a1z); a1w=fmaf(lv1,rn.w,a1w);
    }
    float* pb = partial + wi*256;
    pb[0*64+l]=a0x; pb[1*64+l]=a0y; pb[2*64+l]=a0z; pb[3*64+l]=a0w;
    pb[0*64+l+32]=a1x; pb[1*64+l+32]=a1y; pb[2*64+l+32]=a1z; pb[3*64+l+32]=a1w;
    __syncthreads();
    float sum = 0.f;
    #pragma unroll
    for (int g=0;g<8;g++) sum += partial[g*256 + tid];
    g_rv[b*(RR*WD) + tid] = sum;
}

// ---------------- K6 (final step only) ------------------------------------------
__global__ __launch_bounds__(256) void k_out(const float* __restrict__ Wm,
                                             float* __restrict__ out, int t){
    __shared__ __align__(16) float s[BB*RR*WD];
    int tid = threadIdx.x;
    for (int i=tid;i<BB*RR*WD;i+=256) s[i] = g_rv[i];
    __syncthreads();

    int kg = tid>>5, jl = tid&31;
    int j = blockIdx.x*32 + jl;
    const float* Wc = Wm + j;
    float acc[BB];
    #pragma unroll
    for (int b=0;b<BB;b++) acc[b]=0.f;
    int k0 = kg*32;
    #pragma unroll 2
    for (int kk=0; kk<32; kk+=4){
        int k = k0+kk;
        float w0 = Wc[(k+0)*OO], w1 = Wc[(k+1)*OO], w2 = Wc[(k+2)*OO], w3 = Wc[(k+3)*OO];
        #pragma unroll
        for (int b=0;b<BB;b++){
            float4 v = *reinterpret_cast<const float4*>(&s[b*(RR*WD)+k]);
            acc[b] = fmaf(v.x,w0, fmaf(v.y,w1, fmaf(v.z,w2, fmaf(v.w,w3, acc[b]))));
        }
    }
    __syncthreads();
    #pragma unroll
    for (int b=0;b<BB;b++) s[kg*512 + b*32 + jl] = acc[b];
    __syncthreads();
    for (int p=tid;p<512;p+=256){
        int b = p>>5, jj = p&31;
        int jo = blockIdx.x*32 + jj;
        float sum = g_po[b*OO + jo];
        #pragma unroll
        for (int g=0;g<8;g++) sum += s[g*512 + b*32 + jj];
        out[(t*BB + b)*OO + jo] = sum;
    }
}

// ---------------- launch --------------------------------------------------------
extern "C" void kernel_launch(void* const* d_in, const int* in_sizes, int n_in,
                              void* d_out, int out_size){
    const float* x  = (const float*)d_in[0];
    const float* Wh = (const float*)d_in[1];
    const float* bh = (const float*)d_in[2];
    const float* Wi = (const float*)d_in[3];
    const float* Wo = (const float*)d_in[4];
    const float* Wm = (const float*)d_in[5];
    float* out = (float*)d_out;

    const int smHid  = (BB*NIN + 16*256)*sizeof(float);
    const int smProj = (BB*HH  + 16*256)*sizeof(float);
    cudaFuncSetAttribute(k_hidout, cudaFuncAttributeMaxDynamicSharedMemorySize, smHid);
    cudaFuncSetAttribute(k_proj,   cudaFuncAttributeMaxDynamicSharedMemorySize, smProj);

    k_init<<<512,256>>>();
    for (int t=0;t<TT;t++){
        int par = t & 1;
        k_hidout <<<32,256,smHid>>>(x, Wh, bh, Wm, out, t);
        k_proj   <<<62,256,smProj>>>(Wo, Wi);
        k_wsim   <<<dim3(9,BB),256>>>();
        k_control<<<BB,256>>>(par);
        k_meml   <<<dim3(33,BB),256>>>(par);
        k_read   <<<BB,256>>>();
    }
    k_out<<<16,256>>>(Wm, out, TT-1);
}